// round 15
// baseline (speedup 1.0000x reference)
#include <cuda_runtime.h>

// Graph_Learn: S[n,i,j] = exp(relu(sum_f |xm[n,i,f]-xm[n,j,f]|*a[f])) / colsum_i
// N=8, T=8 (slice t=4), V=512, F=64. Output (8,512,512) fp32.
// Cooperative persistent kernel, 144 CTAs (1/SM with 4-SM headroom -- never
// launch cooperative grids at the exact residency bound), each handles exactly
// 2 tile-pairs with a scalar FADD+FFMA|abs| mainloop (xj + av in registers, no
// LOP3s), then one grid barrier, then normalized writes for both items.

#define NB    8
#define TB    8
#define VB    512
#define FB    64
#define TS    64
#define NT    (VB / TS)                 // 8
#define NPAIR (NT * (NT + 1) / 2)       // 36
#define NITEM (NPAIR * NB)              // 288 work items
#define NBLK  144                       // 288/2; <=148 SMs with headroom

typedef unsigned long long ull;

__device__ float g_partial[NB * NT * VB];   // [n][d][col], each slot written once
__device__ ull   g_bar = 0ull;              // monotone generation counter

// smem (floats): xi[64][64] | xj[64][64] | ev0[64][65] | ev1[64][65] | ps[4][64] | invj[64] | invi[64]
#define SMA_XJ   (TS * FB)
#define SMA_EV0  (2 * TS * FB)
#define SMA_EV1  (SMA_EV0 + TS * 65)
#define SMA_PS   (SMA_EV1 + TS * 65)
#define SMA_IJ   (SMA_PS + 4 * TS)
#define SMA_II   (SMA_IJ + TS)
#define SMA_FLOATS (SMA_II + TS)            // 16992 floats = 67968 B

__device__ __forceinline__ void decode_item(int idx, int& n, int& ti, int& tj) {
    n = idx / NPAIR;
    int rem = idx % NPAIR;
    int t = 0;
    while (rem >= NT - t) { rem -= NT - t; t++; }
    ti = t; tj = t + rem;
}

__global__ __launch_bounds__(256, 1)
void graph_learn_fused(const float* __restrict__ x,
                       const float* __restrict__ a,
                       float* __restrict__ out) {
    extern __shared__ float sm[];
    float* xi   = sm;                 // [64][64]
    float* xj   = sm + SMA_XJ;        // [64][64]
    float* evb[2] = { sm + SMA_EV0, sm + SMA_EV1 };   // [64][65] each
    float* ps   = sm + SMA_PS;        // [4][64]
    float* invj = sm + SMA_IJ;        // [64]
    float* invi = sm + SMA_II;        // [64]

    const int tid = threadIdx.x;
    const int jl  = tid & (TS - 1);   // j within tile (0..63)
    const int ig  = tid >> 6;         // i-group (0..3); 2 warps share an ig

    // a[64] into registers (uniform; L1-resident broadcast loads)
    float av[FB];
    #pragma unroll
    for (int k = 0; k < FB / 4; k++) {
        float4 v = __ldg((const float4*)a + k);
        av[4*k+0] = v.x; av[4*k+1] = v.y; av[4*k+2] = v.z; av[4*k+3] = v.w;
    }

    // ================= compute phase: exactly 2 tile-pairs =================
    #pragma unroll 1
    for (int item = 0; item < 2; item++) {
        const int idx = blockIdx.x + item * NBLK;
        int n, ti, tj; decode_item(idx, n, ti, tj);
        float* ev = evb[item];

        __syncthreads();   // previous item's readers of xi/xj/ps done

        const float* xbase = x + ((size_t)n * TB + TB / 2) * VB * FB;
        {
            const float4* si = (const float4*)(xbase + ti * TS * FB);
            const float4* sj = (const float4*)(xbase + tj * TS * FB);
            float4* xi4 = (float4*)xi;
            float4* xj4 = (float4*)xj;
            #pragma unroll
            for (int q = 0; q < 4; q++) {
                int k = q * 256 + tid;
                xi4[k] = si[k];
                xj4[k] = sj[k];
            }
        }
        __syncthreads();

        // per-thread j-row into registers (64 floats)
        float xjr[FB];
        {
            const float4* jr = (const float4*)(xj + jl * FB);
            #pragma unroll
            for (int k = 0; k < FB / 4; k++) {
                float4 v = jr[k];
                xjr[4*k+0] = v.x; xjr[4*k+1] = v.y;
                xjr[4*k+2] = v.z; xjr[4*k+3] = v.w;
            }
        }

        float csum = 0.f;

        // scalar mainloop: 2 i-rows per iter, 8 accumulators, 2 uniform LDS/k
        #pragma unroll 1
        for (int it = 0; it < TS / 8; it++) {        // 8 iters
            const int i0 = it * 8 + ig * 2;          // warp-uniform
            const int i1 = i0 + 1;
            const float4* r0 = (const float4*)(xi + i0 * FB);
            const float4* r1 = (const float4*)(xi + i1 * FB);
            float a00 = 0.f, a01 = 0.f, a02 = 0.f, a03 = 0.f;
            float a10 = 0.f, a11 = 0.f, a12 = 0.f, a13 = 0.f;
            #pragma unroll
            for (int k = 0; k < FB / 4; k++) {
                float4 v0 = r0[k];
                float4 v1 = r1[k];
                a00 = fmaf(fabsf(v0.x - xjr[4*k+0]), av[4*k+0], a00);
                a01 = fmaf(fabsf(v0.y - xjr[4*k+1]), av[4*k+1], a01);
                a02 = fmaf(fabsf(v0.z - xjr[4*k+2]), av[4*k+2], a02);
                a03 = fmaf(fabsf(v0.w - xjr[4*k+3]), av[4*k+3], a03);
                a10 = fmaf(fabsf(v1.x - xjr[4*k+0]), av[4*k+0], a10);
                a11 = fmaf(fabsf(v1.y - xjr[4*k+1]), av[4*k+1], a11);
                a12 = fmaf(fabsf(v1.z - xjr[4*k+2]), av[4*k+2], a12);
                a13 = fmaf(fabsf(v1.w - xjr[4*k+3]), av[4*k+3], a13);
            }
            float s0 = (a00 + a01) + (a02 + a03);
            float s1 = (a10 + a11) + (a12 + a13);
            float e0 = __expf(fmaxf(s0, 0.f));
            float e1 = __expf(fmaxf(s1, 0.f));
            ev[i0 * 65 + jl] = e0;
            ev[i1 * 65 + jl] = e1;
            csum += e0 + e1;
        }

        // direct partial: rows ti-range, cols tj*64+jl -> slot [n][ti]
        ps[ig * TS + jl] = csum;
        __syncthreads();
        if (tid < TS) {
            float t = ps[tid] + ps[TS + tid] + ps[2 * TS + tid] + ps[3 * TS + tid];
            g_partial[(n * NT + ti) * VB + tj * TS + tid] = t;
        }

        if (ti != tj) {   // block-uniform condition
            // transposed partial: rows tj-range, cols ti*64+jl -> slot [n][tj]
            float rsum = 0.f;
            #pragma unroll
            for (int m = 0; m < TS / 4; m++) {
                rsum += ev[jl * 65 + (m * 4 + ig)];   // stride-65: conflict-free
            }
            __syncthreads();                          // ps readers done
            ps[ig * TS + jl] = rsum;
            __syncthreads();
            if (tid < TS) {
                float t = ps[tid] + ps[TS + tid] + ps[2 * TS + tid] + ps[3 * TS + tid];
                g_partial[(n * NT + tj) * VB + ti * TS + tid] = t;
            }
        }
    }

    // ---- software grid barrier (generation counting, replay-safe;
    //      co-residency guaranteed by cooperative launch, 144 CTAs) ----
    __threadfence();
    __syncthreads();
    if (tid == 0) {
        ull my = atomicAdd(&g_bar, 1ull);
        ull target = (my / NBLK + 1ull) * (ull)NBLK;
        while (*((volatile ull*)&g_bar) < target) { __nanosleep(32); }
    }
    __syncthreads();
    __threadfence();

    // ================= epilogue: normalized writes for both items =================
    #pragma unroll 1
    for (int item = 0; item < 2; item++) {
        const int idx = blockIdx.x + item * NBLK;
        int n, ti, tj; decode_item(idx, n, ti, tj);
        float* ev = evb[item];

        __syncthreads();   // previous item's invj/invi readers done
        if (tid < TS) {
            const float* p = g_partial + n * NT * VB + tj * TS + tid;
            float s = 0.f;
            #pragma unroll
            for (int d = 0; d < NT; d++) s += p[d * VB];
            invj[tid] = 1.0f / s;
        } else if (tid < 2 * TS) {
            const float* p = g_partial + n * NT * VB + ti * TS + (tid - TS);
            float s = 0.f;
            #pragma unroll
            for (int d = 0; d < NT; d++) s += p[d * VB];
            invi[tid - TS] = 1.0f / s;
        }
        __syncthreads();

        float* o = out + (size_t)n * VB * VB;
        {
            const float fj = invj[jl];
            #pragma unroll
            for (int m = 0; m < TS / 4; m++) {
                int ir = m * 4 + ig;
                o[(size_t)(ti * TS + ir) * VB + tj * TS + jl] = ev[ir * 65 + jl] * fj;
            }
        }
        if (ti != tj) {
            const float fi = invi[jl];
            #pragma unroll
            for (int m = 0; m < TS / 4; m++) {
                int jr = m * 4 + ig;
                o[(size_t)(tj * TS + jr) * VB + ti * TS + jl] = ev[jl * 65 + jr] * fi;
            }
        }
    }
}

extern "C" void kernel_launch(void* const* d_in, const int* in_sizes, int n_in,
                              void* d_out, int out_size) {
    const float* x = (const float*)d_in[0];   // (8,8,512,64) fp32
    const float* a = (const float*)d_in[1];   // (64,1) fp32
    float* out = (float*)d_out;               // (8,512,512) fp32

    const int smem_bytes = SMA_FLOATS * (int)sizeof(float);  // 67968 B
    cudaFuncSetAttribute(graph_learn_fused,
                         cudaFuncAttributeMaxDynamicSharedMemorySize, smem_bytes);

    dim3 grid(NBLK, 1);     // 144 CTAs, 1 per SM, headroom below the 148 bound
    dim3 block(256, 1, 1);
    void* args[] = { (void*)&x, (void*)&a, (void*)&out };
    cudaLaunchCooperativeKernel((void*)graph_learn_fused, grid, block,
                                args, (size_t)smem_bytes, (cudaStream_t)0);
}